// round 1
// baseline (speedup 1.0000x reference)
#include <cuda_runtime.h>
#include <math.h>

// ---------------- problem constants ----------------
constexpr int NT   = 2048;   // sequence length
constexpr int MD   = 1024;   // feature dim (M == H)
constexpr int GB   = 128;    // phase-B persistent blocks
constexpr int COLS = 8;      // MD / GB columns per block

// ---------------- device scratch (no allocations allowed) ----------------
__device__ float g_part[6 * 8 * 1024];     // K0 partials: s=0..4 -> P5, s=5 -> molrow
__device__ float g_biasvec[1024];          // molrow + bh_proj_b
__device__ float g_X[NT * MD];
__device__ float g_H[NT * MD];
__device__ float g_U[NT * MD];
__device__ float g_demb[NT * 64];
__device__ float g_ybase[NT * MD];
__device__ float g_xchg[2][MD];
__device__ unsigned int g_arrive;

__device__ __forceinline__ float geluf(float x) {
    return 0.5f * x * (1.0f + erff(x * 0.7071067811865476f));
}
__device__ __forceinline__ float softplusf(float x) {
    return (x > 0.f) ? x + log1pf(expf(-x)) : log1pf(expf(x));
}

// ---------------- reset (per replay) ----------------
__global__ void k_reset() { g_arrive = 0u; }

// ---------------- K0: partials for P5 (s<5) and molrow (s==5) ----------------
__global__ void k0_part(const float* __restrict__ mol_vec,
                        const float* __restrict__ solvent_vecs,
                        const float* __restrict__ sp_proj_w,
                        const float* __restrict__ bh_proj_w) {
    int s = blockIdx.y, chunk = blockIdx.x, tid = threadIdx.x;
    const float* vec = (s < 5) ? (solvent_vecs + s * 1024) : mol_vec;
    const float* W   = (s < 5) ? (sp_proj_w + (size_t)s * 1024 * 1024) : bh_proj_w;
    float acc[4] = {0.f, 0.f, 0.f, 0.f};
    int i0 = chunk * 128;
    for (int i = i0; i < i0 + 128; i++) {
        float v = __ldg(&vec[i]);
        const float* Wr = W + (size_t)i * 1024;
#pragma unroll
        for (int u = 0; u < 4; u++) acc[u] += v * Wr[tid + 256 * u];
    }
#pragma unroll
    for (int u = 0; u < 4; u++)
        g_part[(s * 8 + chunk) * 1024 + tid + 256 * u] = acc[u];
}

// ---------------- K0b: biasvec = molrow + bh_proj_b ----------------
__global__ void k0b(const float* __restrict__ bh_proj_b) {
    int j = blockIdx.x * 256 + threadIdx.x;
    float a = bh_proj_b[j];
#pragma unroll
    for (int p = 0; p < 8; p++) a += g_part[(40 + p) * 1024 + j];
    g_biasvec[j] = a;
}

// ---------------- K1: sp0[t] = gelu(ratios@P5 + sp_proj_b) ----------------
__global__ void k1_sp0(const float* __restrict__ ratios,
                       const float* __restrict__ spb) {
    __shared__ float sr[5];
    int t = blockIdx.x, tid = threadIdx.x;
    if (tid < 5) sr[tid] = ratios[t * 5 + tid];
    __syncthreads();
#pragma unroll
    for (int u = 0; u < 4; u++) {
        int j = tid + 256 * u;
        float acc = spb[j];
#pragma unroll
        for (int s = 0; s < 5; s++) {
            float ps = 0.f;
#pragma unroll
            for (int p = 0; p < 8; p++) ps += g_part[(s * 8 + p) * 1024 + j];
            acc += sr[s] * ps;
        }
        g_X[(size_t)t * 1024 + j] = geluf(acc);
    }
}

// ---------------- demb = gelu(desc@desc_w + desc_b) ----------------
__global__ void k_demb(const float* __restrict__ desc,
                       const float* __restrict__ dw,
                       const float* __restrict__ db) {
    int t = blockIdx.x, j = threadIdx.x;  // 64 threads
    float acc = db[j];
#pragma unroll
    for (int k = 0; k < 6; k++) acc += desc[t * 6 + k] * dw[k * 64 + j];
    g_demb[t * 64 + j] = geluf(acc);
}

// ---------------- generic tiled fp32 GEMM: C = act(A@W + bias + res) ----------------
__global__ void k_gemm(const float* __restrict__ A, int lda,
                       const float* __restrict__ W, int ldw,
                       const float* __restrict__ bias,
                       const float* __restrict__ res,
                       float* __restrict__ C, int N, int K, int act) {
    __shared__ float As[16][64];   // [k][m]
    __shared__ float Ws[16][68];   // [k][n] (+pad, row stride 272B = 16B aligned)
    int tid = threadIdx.x;
    int bx = blockIdx.x, by = blockIdx.y;
    int tx = tid & 15, ty = tid >> 4;
    float acc[4][4] = {};
    int mBase = by * 64, nBase = bx * 64;
    for (int k0 = 0; k0 < K; k0 += 16) {
        int mA = tid >> 2;
        int kA = (tid & 3) * 4;
        float4 av = *reinterpret_cast<const float4*>(&A[(size_t)(mBase + mA) * lda + k0 + kA]);
        As[kA + 0][mA] = av.x; As[kA + 1][mA] = av.y;
        As[kA + 2][mA] = av.z; As[kA + 3][mA] = av.w;
        int kW = tid >> 4;
        int nW = (tid & 15) * 4;
        float4 wv = *reinterpret_cast<const float4*>(&W[(size_t)(k0 + kW) * ldw + nBase + nW]);
        *reinterpret_cast<float4*>(&Ws[kW][nW]) = wv;
        __syncthreads();
#pragma unroll
        for (int kk = 0; kk < 16; kk++) {
            float4 a = *reinterpret_cast<const float4*>(&As[kk][ty * 4]);
            float4 b = *reinterpret_cast<const float4*>(&Ws[kk][tx * 4]);
            float aa[4] = {a.x, a.y, a.z, a.w};
            float bb[4] = {b.x, b.y, b.z, b.w};
#pragma unroll
            for (int i = 0; i < 4; i++)
#pragma unroll
                for (int j = 0; j < 4; j++) acc[i][j] += aa[i] * bb[j];
        }
        __syncthreads();
    }
#pragma unroll
    for (int i = 0; i < 4; i++) {
        int m = mBase + ty * 4 + i;
#pragma unroll
        for (int j = 0; j < 4; j++) {
            int n = nBase + tx * 4 + j;
            float v = acc[i][j];
            if (bias) v += bias[n];
            if (res)  v += res[(size_t)m * N + n];
            if (act)  v = geluf(v);
            C[(size_t)m * N + n] = v;
        }
    }
}

// ---------------- row LayerNorm ----------------
__global__ void k_ln(const float* __restrict__ U, const float* __restrict__ g,
                     const float* __restrict__ b, float* __restrict__ X) {
    __shared__ float red[32];
    int t = blockIdx.x, tid = threadIdx.x;
    float v[4]; float s = 0.f, s2 = 0.f;
#pragma unroll
    for (int u = 0; u < 4; u++) {
        v[u] = U[(size_t)t * 1024 + tid + 256 * u];
        s += v[u]; s2 += v[u] * v[u];
    }
#pragma unroll
    for (int o = 16; o; o >>= 1) {
        s += __shfl_down_sync(~0u, s, o);
        s2 += __shfl_down_sync(~0u, s2, o);
    }
    int lane = tid & 31, w = tid >> 5;
    if (lane == 0) { red[w] = s; red[8 + w] = s2; }
    __syncthreads();
    if (tid == 0) {
        float ts = 0.f, ts2 = 0.f;
#pragma unroll
        for (int q = 0; q < 8; q++) { ts += red[q]; ts2 += red[8 + q]; }
        float m = ts * (1.f / 1024.f);
        float var = ts2 * (1.f / 1024.f) - m * m;
        red[16] = m; red[17] = rsqrtf(var + 1e-5f);
    }
    __syncthreads();
    float m = red[16], rs = red[17];
#pragma unroll
    for (int u = 0; u < 4; u++) {
        int i = tid + 256 * u;
        X[(size_t)t * 1024 + i] = g[i] * (v[u] - m) * rs + b[i];
    }
}

// ---------------- Phase B: persistent sequential kernel ----------------
// 128 blocks; each caches 8 columns of all 6 beta-head matrices in SMEM.
// 6 grid barriers per step (h, u) x 3 blocks. All blocks redundantly compute
// LN stats and mu/phi/rf (bit-identical), so no scalar broadcast is needed.
constexpr int SMEMB_FLOATS = 49152 + 3072 + 3072 + 1024 + 1024 + 24 + 24 + 32 + 8;

__global__ void __launch_bounds__(256, 1) k_seq(
    const float* __restrict__ bh_fc1_w, const float* __restrict__ bh_fc1_b,
    const float* __restrict__ bh_fc2_w, const float* __restrict__ bh_fc2_b,
    const float* __restrict__ bh_ln_g,  const float* __restrict__ bh_ln_b,
    const float* __restrict__ bh_proj_w,
    const float* __restrict__ mu_w, const float* __restrict__ mu_b,
    const float* __restrict__ phi_w, const float* __restrict__ phi_b,
    const unsigned char* __restrict__ bmask,
    float* __restrict__ out) {
    extern __shared__ float sm[];
    float* sW    = sm;             // 6*8*1024
    float* sLnG  = sm + 49152;     // 3*1024
    float* sLnB  = sm + 52224;     // 3*1024
    float* sR    = sm + 55296;     // 1024 (bh_proj_w row 2112)
    float* sX    = sm + 56320;     // 1024 working vector
    float* sB1   = sm + 57344;     // 24
    float* sB2   = sm + 57368;     // 24
    float* sRed  = sm + 57392;     // 32
    float* sScal = sm + 57424;     // 8

    int tid = threadIdx.x, lane = tid & 31, w = tid >> 5;
    int g = blockIdx.x;
    int cg = g * COLS;

    // one-time SMEM weight cache (column-major slices, conflict-free reads)
    for (int m = 0; m < 6; m++) {
        const float* Wg = (m & 1) ? (bh_fc2_w + (size_t)(m >> 1) * 1048576)
                                  : (bh_fc1_w + (size_t)(m >> 1) * 1048576);
        for (int idx = tid; idx < 8192; idx += 256) {
            int c = idx & 7, row = idx >> 3;
            sW[m * 8192 + c * 1024 + row] = Wg[(size_t)row * 1024 + cg + c];
        }
    }
    for (int idx = tid; idx < 3072; idx += 256) {
        sLnG[idx] = bh_ln_g[idx];
        sLnB[idx] = bh_ln_b[idx];
    }
    for (int idx = tid; idx < 1024; idx += 256)
        sR[idx] = bh_proj_w[(size_t)2112 * 1024 + idx];
    if (tid < 24) {
        int i = tid / 8, c = tid % 8;
        sB1[tid] = bh_fc1_b[i * 1024 + cg + c];
        sB2[tid] = bh_fc2_b[i * 1024 + cg + c];
    }
    __syncthreads();

    float prev = -1.f;
    unsigned xn = 0;
    float mub = mu_b[0], phib = phi_b[0];

    for (int t = 0; t < NT; t++) {
        // z0 = gelu(ybase[t] + prev * r) — fully local
#pragma unroll
        for (int u = 0; u < 4; u++) {
            int i = tid + 256 * u;
            sX[i] = geluf(g_ybase[(size_t)t * 1024 + i] + prev * sR[i]);
        }
        __syncthreads();

        for (int blk = 0; blk < 3; blk++) {
            float xres = sX[cg + w];  // residual slice value (broadcast read)

            // ---- h = gelu(x @ W1 + b1), this block's 8 columns ----
            {
                const float* wc = &sW[(2 * blk) * 8192 + w * 1024];
                float acc = 0.f;
#pragma unroll
                for (int k = 0; k < 32; k++) {
                    int i = lane + 32 * k;
                    acc += sX[i] * wc[i];
                }
#pragma unroll
                for (int o = 16; o; o >>= 1) acc += __shfl_down_sync(~0u, acc, o);
                int bi = xn & 1;
                if (lane == 0) g_xchg[bi][cg + w] = geluf(acc + sB1[blk * 8 + w]);
                xn++;
                __syncthreads();
                __threadfence();
                if (tid == 0) {
                    atomicAdd(&g_arrive, 1u);
                    unsigned target = xn * GB, v;
                    do {
                        asm volatile("ld.acquire.gpu.u32 %0,[%1];" : "=r"(v) : "l"(&g_arrive));
                    } while (v < target);
                }
                __syncthreads();
                // pull full h into sX
#pragma unroll
                for (int u = 0; u < 4; u++) {
                    int i = tid + 256 * u;
                    sX[i] = g_xchg[bi][i];
                }
                __syncthreads();
            }

            // ---- u = h @ W2 + b2 + x ----
            int bi2;
            {
                const float* wc = &sW[(2 * blk + 1) * 8192 + w * 1024];
                float acc = 0.f;
#pragma unroll
                for (int k = 0; k < 32; k++) {
                    int i = lane + 32 * k;
                    acc += sX[i] * wc[i];
                }
#pragma unroll
                for (int o = 16; o; o >>= 1) acc += __shfl_down_sync(~0u, acc, o);
                bi2 = xn & 1;
                if (lane == 0) g_xchg[bi2][cg + w] = acc + sB2[blk * 8 + w] + xres;
                xn++;
                __syncthreads();
                __threadfence();
                if (tid == 0) {
                    atomicAdd(&g_arrive, 1u);
                    unsigned target = xn * GB, v;
                    do {
                        asm volatile("ld.acquire.gpu.u32 %0,[%1];" : "=r"(v) : "l"(&g_arrive));
                    } while (v < target);
                }
                __syncthreads();
            }

            // ---- LayerNorm (local, identical in every block) ----
            float uv[4], s = 0.f, s2 = 0.f;
#pragma unroll
            for (int u = 0; u < 4; u++) {
                uv[u] = g_xchg[bi2][tid + 256 * u];
                s += uv[u]; s2 += uv[u] * uv[u];
            }
#pragma unroll
            for (int o = 16; o; o >>= 1) {
                s += __shfl_down_sync(~0u, s, o);
                s2 += __shfl_down_sync(~0u, s2, o);
            }
            if (lane == 0) { sRed[w] = s; sRed[8 + w] = s2; }
            __syncthreads();
            if (tid == 0) {
                float ts = 0.f, ts2 = 0.f;
#pragma unroll
                for (int q = 0; q < 8; q++) { ts += sRed[q]; ts2 += sRed[8 + q]; }
                float mm = ts * (1.f / 1024.f);
                float var = ts2 * (1.f / 1024.f) - mm * mm;
                sScal[0] = mm;
                sScal[1] = rsqrtf(var + 1e-5f);
            }
            __syncthreads();
            float mm = sScal[0], rs = sScal[1];
            const float* lg = &sLnG[blk * 1024];
            const float* lb = &sLnB[blk * 1024];
#pragma unroll
            for (int u = 0; u < 4; u++) {
                int i = tid + 256 * u;
                sX[i] = lg[i] * (uv[u] - mm) * rs + lb[i];
            }
            __syncthreads();
        }

        // ---- mu / phi / rf (redundant identical computation per block) ----
        float pm = 0.f, pp = 0.f;
#pragma unroll
        for (int u = 0; u < 4; u++) {
            int i = tid + 256 * u;
            float xv = sX[i];
            pm += xv * mu_w[i];
            pp += xv * phi_w[i];
        }
#pragma unroll
        for (int o = 16; o; o >>= 1) {
            pm += __shfl_down_sync(~0u, pm, o);
            pp += __shfl_down_sync(~0u, pp, o);
        }
        if (lane == 0) { sRed[w] = pm; sRed[8 + w] = pp; }
        __syncthreads();
        if (tid == 0) {
            float tm = 0.f, tp = 0.f;
#pragma unroll
            for (int q = 0; q < 8; q++) { tm += sRed[q]; tp += sRed[8 + q]; }
            float mu = 1.f / (1.f + expf(-(tm + mub)));
            float phi = softplusf(tp + phib) + 2.f;
            bool isb = (bmask[t] != 0);
            float rf = (isb || prev < 0.f) ? mu : prev + mu * (1.f - prev);
            sScal[2] = rf;
            if (g == 0) {
                out[t] = rf;
                out[NT + t] = mu;
                out[2 * NT + t] = phi;
            }
        }
        __syncthreads();
        prev = sScal[2];
    }
}

// ---------------- launch ----------------
extern "C" void kernel_launch(void* const* d_in, const int* in_sizes, int n_in,
                              void* d_out, int out_size) {
    const float* mol_vec      = (const float*)d_in[0];
    const float* solvent_seq  = (const float*)d_in[1];
    const float* desc_seq     = (const float*)d_in[2];
    const float* solvent_vecs = (const float*)d_in[3];
    const unsigned char* bmask = (const unsigned char*)d_in[4];
    const float* sp_proj_w = (const float*)d_in[5];
    const float* sp_proj_b = (const float*)d_in[6];
    const float* sp_fc1_w  = (const float*)d_in[7];
    const float* sp_fc1_b  = (const float*)d_in[8];
    const float* sp_fc2_w  = (const float*)d_in[9];
    const float* sp_fc2_b  = (const float*)d_in[10];
    const float* sp_ln_g   = (const float*)d_in[11];
    const float* sp_ln_b   = (const float*)d_in[12];
    const float* desc_w    = (const float*)d_in[13];
    const float* desc_b    = (const float*)d_in[14];
    const float* bh_proj_w = (const float*)d_in[15];
    const float* bh_proj_b = (const float*)d_in[16];
    const float* bh_fc1_w  = (const float*)d_in[17];
    const float* bh_fc1_b  = (const float*)d_in[18];
    const float* bh_fc2_w  = (const float*)d_in[19];
    const float* bh_fc2_b  = (const float*)d_in[20];
    const float* bh_ln_g   = (const float*)d_in[21];
    const float* bh_ln_b   = (const float*)d_in[22];
    const float* mu_w      = (const float*)d_in[23];
    const float* mu_b      = (const float*)d_in[24];
    const float* phi_w     = (const float*)d_in[25];
    const float* phi_b     = (const float*)d_in[26];
    float* out = (float*)d_out;

    float *pX, *pH, *pU, *pD, *pY, *pBias;
    cudaGetSymbolAddress((void**)&pX, g_X);
    cudaGetSymbolAddress((void**)&pH, g_H);
    cudaGetSymbolAddress((void**)&pU, g_U);
    cudaGetSymbolAddress((void**)&pD, g_demb);
    cudaGetSymbolAddress((void**)&pY, g_ybase);
    cudaGetSymbolAddress((void**)&pBias, g_biasvec);

    k_reset<<<1, 1>>>();
    k0_part<<<dim3(8, 6), 256>>>(mol_vec, solvent_vecs, sp_proj_w, bh_proj_w);
    k0b<<<4, 256>>>(bh_proj_b);
    k1_sp0<<<NT, 256>>>(solvent_seq, sp_proj_b);

    // SolventProjection residual blocks (batched over all t)
    for (int i = 0; i < 3; i++) {
        k_gemm<<<dim3(16, 32), 256>>>(pX, 1024, sp_fc1_w + (size_t)i * 1048576, 1024,
                                      sp_fc1_b + i * 1024, nullptr, pH, 1024, 1024, 1);
        k_gemm<<<dim3(16, 32), 256>>>(pH, 1024, sp_fc2_w + (size_t)i * 1048576, 1024,
                                      sp_fc2_b + i * 1024, pX, pU, 1024, 1024, 0);
        k_ln<<<NT, 256>>>(pU, sp_ln_g + i * 1024, sp_ln_b + i * 1024, pX);
    }

    k_demb<<<NT, 64>>>(desc_seq, desc_w, desc_b);

    // ybase = mol@Wm + sp@Ws + demb@Wd + bh_proj_b  (prev_rf term applied in phase B)
    k_gemm<<<dim3(16, 32), 256>>>(pX, 1024, bh_proj_w + (size_t)1024 * 1024, 1024,
                                  pBias, nullptr, pH, 1024, 1024, 0);
    k_gemm<<<dim3(16, 32), 256>>>(pD, 64, bh_proj_w + (size_t)2048 * 1024, 1024,
                                  nullptr, pH, pY, 1024, 64, 0);

    // Phase B: persistent sequential kernel
    cudaFuncSetAttribute(k_seq, cudaFuncAttributeMaxDynamicSharedMemorySize,
                         SMEMB_FLOATS * (int)sizeof(float));
    k_seq<<<GB, 256, SMEMB_FLOATS * sizeof(float)>>>(
        bh_fc1_w, bh_fc1_b, bh_fc2_w, bh_fc2_b, bh_ln_g, bh_ln_b, bh_proj_w,
        mu_w, mu_b, phi_w, phi_b, bmask, out);
}